// round 1
// baseline (speedup 1.0000x reference)
#include <cuda_runtime.h>

#define TPB 128

// x:      (4, 32, 56, 56) f32
// weight: (4, 4, 9, 8, 16) f32   [o][p][k][l][d]
// out:    (4, 64, 56, 56) f32    channel = o*16 + d
//
// One thread per (n, o, h, w); loops p internally; priors + routing fully
// register-resident; weight slice for this block's o staged in shared memory.

__global__ void __launch_bounds__(TPB) caps_kernel(
    const float* __restrict__ x,
    const float* __restrict__ wgt,
    float* __restrict__ out)
{
    __shared__ float sw[4608];  // [p][k][l][d] for this o : 4*9*8*16
    const int o = blockIdx.y;
    const int n = blockIdx.z;

    // Stage weight[o] into shared (float4, fully coalesced, 9 iters/thread)
    {
        const float4* src = reinterpret_cast<const float4*>(wgt) + o * 1152;
        float4* dst = reinterpret_cast<float4*>(sw);
        #pragma unroll
        for (int i = 0; i < 9; ++i)
            dst[threadIdx.x + i * TPB] = src[threadIdx.x + i * TPB];
    }
    __syncthreads();

    const int s = blockIdx.x * TPB + threadIdx.x;
    if (s >= 3136) return;
    const int h = s / 56;
    const int w = s - h * 56;

    const bool ht = (h > 0), hb = (h < 55);
    const bool wl = (w > 0), wr = (w < 55);

    float outsum[16];
    #pragma unroll
    for (int d = 0; d < 16; ++d) outsum[d] = 0.0f;

    const float4* swf4 = reinterpret_cast<const float4*>(sw);

    #pragma unroll 1
    for (int p = 0; p < 4; ++p) {
        // ---- priors[k][d] = sum_l patch[l][k] * w[o][p][k][l][d] ----
        float pri[144];
        #pragma unroll
        for (int i = 0; i < 144; ++i) pri[i] = 0.0f;

        const float* xc0 = x + (n * 32 + p * 8) * 3136 + s;

        #pragma unroll 2
        for (int l = 0; l < 8; ++l) {
            const float* xc = xc0 + l * 3136;
            float pt[9];
            pt[0] = (ht && wl) ? __ldg(xc - 57) : 0.0f;
            pt[1] = (ht)       ? __ldg(xc - 56) : 0.0f;
            pt[2] = (ht && wr) ? __ldg(xc - 55) : 0.0f;
            pt[3] = (wl)       ? __ldg(xc - 1)  : 0.0f;
            pt[4] =              __ldg(xc);
            pt[5] = (wr)       ? __ldg(xc + 1)  : 0.0f;
            pt[6] = (hb && wl) ? __ldg(xc + 55) : 0.0f;
            pt[7] = (hb)       ? __ldg(xc + 56) : 0.0f;
            pt[8] = (hb && wr) ? __ldg(xc + 57) : 0.0f;

            const float4* wpl = swf4 + p * 288 + l * 4;  // float4 units
            #pragma unroll
            for (int k = 0; k < 9; ++k) {
                const float4 w0 = wpl[k * 32 + 0];
                const float4 w1 = wpl[k * 32 + 1];
                const float4 w2 = wpl[k * 32 + 2];
                const float4 w3 = wpl[k * 32 + 3];
                const float pk = pt[k];
                pri[k*16 +  0] = fmaf(pk, w0.x, pri[k*16 +  0]);
                pri[k*16 +  1] = fmaf(pk, w0.y, pri[k*16 +  1]);
                pri[k*16 +  2] = fmaf(pk, w0.z, pri[k*16 +  2]);
                pri[k*16 +  3] = fmaf(pk, w0.w, pri[k*16 +  3]);
                pri[k*16 +  4] = fmaf(pk, w1.x, pri[k*16 +  4]);
                pri[k*16 +  5] = fmaf(pk, w1.y, pri[k*16 +  5]);
                pri[k*16 +  6] = fmaf(pk, w1.z, pri[k*16 +  6]);
                pri[k*16 +  7] = fmaf(pk, w1.w, pri[k*16 +  7]);
                pri[k*16 +  8] = fmaf(pk, w2.x, pri[k*16 +  8]);
                pri[k*16 +  9] = fmaf(pk, w2.y, pri[k*16 +  9]);
                pri[k*16 + 10] = fmaf(pk, w2.z, pri[k*16 + 10]);
                pri[k*16 + 11] = fmaf(pk, w2.w, pri[k*16 + 11]);
                pri[k*16 + 12] = fmaf(pk, w3.x, pri[k*16 + 12]);
                pri[k*16 + 13] = fmaf(pk, w3.y, pri[k*16 + 13]);
                pri[k*16 + 14] = fmaf(pk, w3.z, pri[k*16 + 14]);
                pri[k*16 + 15] = fmaf(pk, w3.w, pri[k*16 + 15]);
            }
        }

        // ---- dynamic routing: 3 iterations, softmax over K=9 ----
        float logits[9];
        #pragma unroll
        for (int k = 0; k < 9; ++k) logits[k] = 0.0f;

        #pragma unroll 1
        for (int it = 0; it < 3; ++it) {
            float mx = logits[0];
            #pragma unroll
            for (int k = 1; k < 9; ++k) mx = fmaxf(mx, logits[k]);
            float pr[9];
            float sum = 0.0f;
            #pragma unroll
            for (int k = 0; k < 9; ++k) {
                pr[k] = __expf(logits[k] - mx);
                sum += pr[k];
            }
            const float inv = __fdividef(1.0f, sum);

            float sv[16];
            #pragma unroll
            for (int d = 0; d < 16; ++d) sv[d] = 0.0f;
            #pragma unroll
            for (int k = 0; k < 9; ++k) {
                const float pk = pr[k] * inv;
                #pragma unroll
                for (int d = 0; d < 16; ++d)
                    sv[d] = fmaf(pk, pri[k*16 + d], sv[d]);
            }

            float sq = 0.0f;
            #pragma unroll
            for (int d = 0; d < 16; ++d) sq = fmaf(sv[d], sv[d], sq);
            // squash scale: |s| / (1 + |s|^2)
            const float f = sqrtf(sq) * __fdividef(1.0f, 1.0f + sq);

            if (it < 2) {
                // logits[k] += sum_d pri[k][d] * (sv[d] * f)  (f factored out)
                #pragma unroll
                for (int k = 0; k < 9; ++k) {
                    float dl = 0.0f;
                    #pragma unroll
                    for (int d = 0; d < 16; ++d)
                        dl = fmaf(pri[k*16 + d], sv[d], dl);
                    logits[k] = fmaf(f, dl, logits[k]);
                }
            } else {
                #pragma unroll
                for (int d = 0; d < 16; ++d)
                    outsum[d] = fmaf(sv[d], f, outsum[d]);
            }
        }
    }

    // ---- write: out[n][o*16+d][h][w], coalesced across threads per d ----
    float* ob = out + (n * 4 + o) * 16 * 3136 + s;
    #pragma unroll
    for (int d = 0; d < 16; ++d) ob[d * 3136] = outsum[d];
}

extern "C" void kernel_launch(void* const* d_in, const int* in_sizes, int n_in,
                              void* d_out, int out_size) {
    const float* x   = (const float*)d_in[0];
    const float* wgt = (const float*)d_in[1];
    float* out = (float*)d_out;

    dim3 grid((3136 + TPB - 1) / TPB, 4, 4);  // (25, o=4, n=4)
    caps_kernel<<<grid, TPB>>>(x, wgt, out);
}

// round 2
// speedup vs baseline: 1.1125x; 1.1125x over previous
#include <cuda_runtime.h>

#define TPB 128
typedef unsigned long long ull;

// x:      (4, 32, 56, 56) f32
// weight: (4, 4, 9, 8, 16) f32   [o][p][k][l][d]
// out:    (4, 64, 56, 56) f32    channel = o*16 + d
//
// Two lanes per site (even lane: d0-7, odd lane: d8-15), f32x2 packed math.
// priors + routing register-resident; weights staged in shared.

__device__ __forceinline__ ull fma2(ull a, ull b, ull c) {
    ull d;
    asm("fma.rn.f32x2 %0, %1, %2, %3;" : "=l"(d) : "l"(a), "l"(b), "l"(c));
    return d;
}
__device__ __forceinline__ ull pack2(float x, float y) {
    ull r;
    asm("mov.b64 %0, {%1, %2};" : "=l"(r) : "f"(x), "f"(y));
    return r;
}
__device__ __forceinline__ float2 unpack2(ull v) {
    float2 r;
    asm("mov.b64 {%0, %1}, %2;" : "=f"(r.x), "=f"(r.y) : "l"(v));
    return r;
}

__global__ void __launch_bounds__(TPB, 3) caps_kernel(
    const float* __restrict__ x,
    const float* __restrict__ wgt,
    float* __restrict__ out)
{
    __shared__ float sw[4608];  // weight[o]: [p][k][l][d] = 4*9*8*16
    const int o = blockIdx.y;
    const int n = blockIdx.z;

    // Stage weight[o] into shared (float4, coalesced, 9 iters/thread)
    {
        const float4* src = reinterpret_cast<const float4*>(wgt) + o * 1152;
        float4* dst = reinterpret_cast<float4*>(sw);
        #pragma unroll
        for (int i = 0; i < 9; ++i)
            dst[threadIdx.x + i * TPB] = src[threadIdx.x + i * TPB];
    }
    __syncthreads();

    const int tid  = threadIdx.x;
    const int half = tid & 1;                     // which 8-d half this lane owns
    const int s    = blockIdx.x * (TPB / 2) + (tid >> 1);   // spatial site (3136 = 49*64, exact)
    const int h = s / 56;
    const int w = s - h * 56;

    const bool ht = (h > 0), hb = (h < 55);
    const bool wl = (w > 0), wr = (w < 55);

    ull outs[4];
    #pragma unroll
    for (int j = 0; j < 4; ++j) outs[j] = 0ull;   // bit pattern 0 == (0.f, 0.f)

    #pragma unroll 1
    for (int p = 0; p < 4; ++p) {
        // ---- priors[k][own 8 d's] as 4 f32x2 pairs per k ----
        ull pri[36];
        #pragma unroll
        for (int i = 0; i < 36; ++i) pri[i] = 0ull;

        const float* xc0 = x + (n * 32 + p * 8) * 3136 + s;
        // base of this lane's weight half in 16B units: ((p*9+k)*8 + l)*16 + half*8 floats
        const ulonglong2* swu2 = reinterpret_cast<const ulonglong2*>(sw);

        #pragma unroll 2
        for (int l = 0; l < 8; ++l) {
            const float* xc = xc0 + l * 3136;
            float pt[9];
            pt[0] = (ht && wl) ? __ldg(xc - 57) : 0.0f;
            pt[1] = (ht)       ? __ldg(xc - 56) : 0.0f;
            pt[2] = (ht && wr) ? __ldg(xc - 55) : 0.0f;
            pt[3] = (wl)       ? __ldg(xc - 1)  : 0.0f;
            pt[4] =              __ldg(xc);
            pt[5] = (wr)       ? __ldg(xc + 1)  : 0.0f;
            pt[6] = (hb && wl) ? __ldg(xc + 55) : 0.0f;
            pt[7] = (hb)       ? __ldg(xc + 56) : 0.0f;
            pt[8] = (hb && wr) ? __ldg(xc + 57) : 0.0f;

            // ulonglong2 index: (((p*9+k)*8+l)*16 + half*8) / 4
            const ulonglong2* wb = swu2 + (p * 72 + l) * 4 + half * 2;
            #pragma unroll
            for (int k = 0; k < 9; ++k) {
                const ulonglong2 wa = wb[k * 32];       // d+0..3 of this half
                const ulonglong2 wc = wb[k * 32 + 1];   // d+4..7 of this half
                const ull pkk = pack2(pt[k], pt[k]);
                pri[k*4 + 0] = fma2(pkk, wa.x, pri[k*4 + 0]);
                pri[k*4 + 1] = fma2(pkk, wa.y, pri[k*4 + 1]);
                pri[k*4 + 2] = fma2(pkk, wc.x, pri[k*4 + 2]);
                pri[k*4 + 3] = fma2(pkk, wc.y, pri[k*4 + 3]);
            }
        }

        // ---- dynamic routing: 3 iterations, softmax over K=9 ----
        float logits[9];
        #pragma unroll
        for (int k = 0; k < 9; ++k) logits[k] = 0.0f;

        #pragma unroll 1
        for (int it = 0; it < 3; ++it) {
            float mx = logits[0];
            #pragma unroll
            for (int k = 1; k < 9; ++k) mx = fmaxf(mx, logits[k]);
            float pr[9];
            float sum = 0.0f;
            #pragma unroll
            for (int k = 0; k < 9; ++k) {
                pr[k] = __expf(logits[k] - mx);
                sum += pr[k];
            }
            const float inv = __fdividef(1.0f, sum);

            ull sv[4];
            #pragma unroll
            for (int j = 0; j < 4; ++j) sv[j] = 0ull;
            #pragma unroll
            for (int k = 0; k < 9; ++k) {
                const float pk = pr[k] * inv;
                const ull pkk = pack2(pk, pk);
                #pragma unroll
                for (int j = 0; j < 4; ++j)
                    sv[j] = fma2(pkk, pri[k*4 + j], sv[j]);
            }

            // |s|^2 over all 16 d: own 8 + partner half via shfl_xor(1)
            ull acc = 0ull;
            #pragma unroll
            for (int j = 0; j < 4; ++j) acc = fma2(sv[j], sv[j], acc);
            const float2 a2 = unpack2(acc);
            const float sqo = a2.x + a2.y;
            const float sq = sqo + __shfl_xor_sync(0xffffffffu, sqo, 1);
            // squash scale: |s| / (1 + |s|^2)
            const float f = sqrtf(sq) * __fdividef(1.0f, 1.0f + sq);

            if (it < 2) {
                #pragma unroll
                for (int k = 0; k < 9; ++k) {
                    ull da = 0ull;
                    #pragma unroll
                    for (int j = 0; j < 4; ++j)
                        da = fma2(pri[k*4 + j], sv[j], da);
                    const float2 d2 = unpack2(da);
                    const float dlo = d2.x + d2.y;
                    const float dl = dlo + __shfl_xor_sync(0xffffffffu, dlo, 1);
                    logits[k] = fmaf(f, dl, logits[k]);
                }
            } else {
                const ull ff = pack2(f, f);
                #pragma unroll
                for (int j = 0; j < 4; ++j)
                    outs[j] = fma2(sv[j], ff, outs[j]);
            }
        }
    }

    // ---- write: out[n][o*16 + half*8 + j][h][w] ----
    float* ob = out + ((n * 4 + o) * 16 + half * 8) * 3136 + s;
    #pragma unroll
    for (int j = 0; j < 4; ++j) {
        const float2 v = unpack2(outs[j]);
        ob[(2*j    ) * 3136] = v.x;
        ob[(2*j + 1) * 3136] = v.y;
    }
}

extern "C" void kernel_launch(void* const* d_in, const int* in_sizes, int n_in,
                              void* d_out, int out_size) {
    const float* x   = (const float*)d_in[0];
    const float* wgt = (const float*)d_in[1];
    float* out = (float*)d_out;

    dim3 grid(3136 / (TPB / 2), 4, 4);  // (49, o=4, n=4)
    caps_kernel<<<grid, TPB>>>(x, wgt, out);
}